// round 3
// baseline (speedup 1.0000x reference)
#include <cuda_runtime.h>
#include <math.h>

#define BATCH  128
#define KK     512
#define JCH    4      // column chunks of 128
#define ISPL   4      // i-dimension splits (128 rows each)
#define TPB    128

#define LOGK 6.2383246250395077632f   // log(512)

// Scratch (__device__ globals; allocation-free rule). Fully overwritten per launch.
__device__ float g_Ep[2 * ISPL * BATCH * KK];   // partial col-sums for Q0/Q1 (2 MB)
__device__ float g_mmp[ISPL * BATCH * KK];      // partial mm sums (1 MB)
__device__ float g_sb[BATCH];                   // per-batch logK - log(sum_j t)
__device__ unsigned int g_ticket;               // zero-init; last block resets it

// ---------------------------------------------------------------------------
// Kernel 1: partial column sums of exp() for Q0 and Q1.
// grid = (JCH, BATCH, 2*ISPL), block = 128. Each block: 128 rows x 128 cols.
// ---------------------------------------------------------------------------
__global__ void __launch_bounds__(TPB) k_colsum(const float* __restrict__ Q0,
                                                const float* __restrict__ Q1)
{
    const int j     = blockIdx.x * TPB + threadIdx.x;
    const int b     = blockIdx.y;
    const int which = blockIdx.z >> 2;      // 0 -> Q0, 1 -> Q1
    const int slice = blockIdx.z & 3;       // i slice

    const float* __restrict__ src = which ? Q1 : Q0;
    const float* p = src + (size_t)b * KK * KK + (size_t)(slice * 128) * KK + j;

    float s0 = 0.f, s1 = 0.f, s2 = 0.f, s3 = 0.f;
    for (int i = 0; i < 128; i += 8) {
        float a0 = p[(size_t)(i + 0) * KK];
        float a1 = p[(size_t)(i + 1) * KK];
        float a2 = p[(size_t)(i + 2) * KK];
        float a3 = p[(size_t)(i + 3) * KK];
        float a4 = p[(size_t)(i + 4) * KK];
        float a5 = p[(size_t)(i + 5) * KK];
        float a6 = p[(size_t)(i + 6) * KK];
        float a7 = p[(size_t)(i + 7) * KK];
        s0 += __expf(a0); s1 += __expf(a1);
        s2 += __expf(a2); s3 += __expf(a3);
        s0 += __expf(a4); s1 += __expf(a5);
        s2 += __expf(a6); s3 += __expf(a7);
    }
    g_Ep[((which * ISPL + slice) * BATCH + b) * KK + j] = (s0 + s1) + (s2 + s3);
}

// ---------------------------------------------------------------------------
// Kernel 2: partial mm[b,j] = sum_{i in slice} ew[b,i] * exp(P1[b,i,j]),
// with ew computed inline from g_Ep + P0.
// grid = (JCH, BATCH, ISPL), block = 128.
// ---------------------------------------------------------------------------
__global__ void __launch_bounds__(TPB) k_mid(const float* __restrict__ P0,
                                             const float* __restrict__ P1)
{
    const int j     = blockIdx.x * TPB + threadIdx.x;
    const int b     = blockIdx.y;
    const int slice = blockIdx.z;
    const int i0    = slice * 128;

    __shared__ float ew[128];
    {
        const int i = i0 + threadIdx.x;     // this block's 128 i-values
        float e1 = 0.f;
#pragma unroll
        for (int s = 0; s < ISPL; s++)
            e1 += g_Ep[((ISPL + s) * BATCH + b) * KK + i];
        ew[threadIdx.x] = __expf(P0[b * KK + i]) * (float)KK / e1;
    }
    __syncthreads();

    const float* p = P1 + (size_t)b * KK * KK + (size_t)i0 * KK + j;

    float s0 = 0.f, s1 = 0.f, s2 = 0.f, s3 = 0.f;
    for (int i = 0; i < 128; i += 8) {
        float a0 = p[(size_t)(i + 0) * KK];
        float a1 = p[(size_t)(i + 1) * KK];
        float a2 = p[(size_t)(i + 2) * KK];
        float a3 = p[(size_t)(i + 3) * KK];
        float a4 = p[(size_t)(i + 4) * KK];
        float a5 = p[(size_t)(i + 5) * KK];
        float a6 = p[(size_t)(i + 6) * KK];
        float a7 = p[(size_t)(i + 7) * KK];
        s0 += ew[i + 0] * __expf(a0);
        s1 += ew[i + 1] * __expf(a1);
        s2 += ew[i + 2] * __expf(a2);
        s3 += ew[i + 3] * __expf(a3);
        s0 += ew[i + 4] * __expf(a4);
        s1 += ew[i + 5] * __expf(a5);
        s2 += ew[i + 6] * __expf(a6);
        s3 += ew[i + 7] * __expf(a7);
    }
    g_mmp[(slice * BATCH + b) * KK + j] = (s0 + s1) + (s2 + s3);
}

// ---------------------------------------------------------------------------
// Kernel 3 (fused final): per-batch s[b] = sum_j (sum_s mmp)/E0 * exp(P2);
// g_sb[b] = logK - log(s[b]); the LAST block to finish sums g_sb into out[0]
// (deterministic: one block, fixed tree order) and resets the ticket.
// grid = BATCH, block = 256 (2 j's per thread).
// ---------------------------------------------------------------------------
__global__ void __launch_bounds__(256) k_final(const float* __restrict__ P2,
                                               float* __restrict__ out)
{
    const int b = blockIdx.x;
    const int t = threadIdx.x;

    float acc = 0.f;
#pragma unroll
    for (int jj = 0; jj < 2; jj++) {
        const int j = jj * 256 + t;
        float m = 0.f, e0 = 0.f;
#pragma unroll
        for (int s = 0; s < ISPL; s++) {
            m  += g_mmp[(s * BATCH + b) * KK + j];
            e0 += g_Ep [(s * BATCH + b) * KK + j];   // which=0 partials
        }
        acc += m / e0 * __expf(P2[b * KK + j]);
    }

    // deterministic block reduction over 256 threads
#pragma unroll
    for (int o = 16; o; o >>= 1)
        acc += __shfl_down_sync(0xFFFFFFFFu, acc, o);

    __shared__ float red[8];
    if ((t & 31) == 0) red[t >> 5] = acc;
    __syncthreads();

    __shared__ bool amLast;
    if (t == 0) {
        float r = ((red[0] + red[1]) + (red[2] + red[3])) +
                  ((red[4] + red[5]) + (red[6] + red[7]));
        g_sb[b] = LOGK - logf(r);
        __threadfence();
        unsigned int n = atomicAdd(&g_ticket, 1u);
        amLast = (n == BATCH - 1);
    }
    __syncthreads();

    if (amLast) {
        // one block: deterministic fixed-order tree sum of g_sb[0..127]
        __shared__ float sm[BATCH];
        if (t < BATCH) sm[t] = g_sb[t];
        __syncthreads();
#pragma unroll
        for (int off = BATCH / 2; off > 0; off >>= 1) {
            if (t < off) sm[t] += sm[t + off];
            __syncthreads();
        }
        if (t == 0) {
            out[0] = sm[0];
            g_ticket = 0;   // reset for next graph replay
        }
    }
}

// ---------------------------------------------------------------------------
extern "C" void kernel_launch(void* const* d_in, const int* in_sizes, int n_in,
                              void* d_out, int out_size)
{
    const float* Q0 = (const float*)d_in[0];  // logQ0 [B,K,K]
    const float* Q1 = (const float*)d_in[1];  // logQ1 [B,K,K]
    const float* P0 = (const float*)d_in[2];  // logP0 [B,1,K]
    const float* P1 = (const float*)d_in[3];  // logP1 [B,K,K]
    const float* P2 = (const float*)d_in[4];  // logP2 [B,K,1]

    dim3 g1(JCH, BATCH, 2 * ISPL);
    k_colsum<<<g1, TPB>>>(Q0, Q1);

    dim3 g2(JCH, BATCH, ISPL);
    k_mid<<<g2, TPB>>>(P0, P1);

    k_final<<<BATCH, 256>>>(P2, (float*)d_out);
}

// round 4
// speedup vs baseline: 1.0033x; 1.0033x over previous
#include <cuda_runtime.h>
#include <math.h>

#define BATCH  128
#define KK     512
#define NSL    16     // i-slices of 32 rows
#define TPB    128    // threads per block; each thread owns 4 columns (float4)

#define LOGK 6.2383246250395077632f   // log(512)

// Scratch (__device__ globals; allocation-free rule). Fully overwritten per launch.
__device__ float g_Ep[2 * NSL * BATCH * KK];   // partial col-sums Q0/Q1 (8 MB)
__device__ float g_mmp[NSL * BATCH * KK];      // partial mm sums (4 MB)
__device__ float g_ew[BATCH * KK];             // exp(P0)*K/E1 (256 KB)
__device__ float g_sb[BATCH];
__device__ unsigned int g_ticket;              // zero-init; last block resets

// ---------------------------------------------------------------------------
// Kernel 1: partial column sums of exp() for Q0 and Q1, float4-vectorized.
// grid = (32, BATCH): x = which*16 + slice. block = 128; thread owns 4 cols.
// Each block: 32 rows x 512 cols.
// ---------------------------------------------------------------------------
__global__ void __launch_bounds__(TPB) k_colsum(const float* __restrict__ Q0,
                                                const float* __restrict__ Q1)
{
    const int which = blockIdx.x >> 4;
    const int slice = blockIdx.x & 15;
    const int b     = blockIdx.y;
    const int t     = threadIdx.x;

    const float* __restrict__ src = which ? Q1 : Q0;
    const float4* p = (const float4*)(src + (size_t)b * KK * KK
                                          + (size_t)(slice * 32) * KK) + t;
    const int rs = KK / 4;   // row stride in float4

    float sx = 0.f, sy = 0.f, sz = 0.f, sw = 0.f;
#pragma unroll
    for (int i = 0; i < 32; i += 8) {
        float4 a0 = p[(i + 0) * rs];
        float4 a1 = p[(i + 1) * rs];
        float4 a2 = p[(i + 2) * rs];
        float4 a3 = p[(i + 3) * rs];
        float4 a4 = p[(i + 4) * rs];
        float4 a5 = p[(i + 5) * rs];
        float4 a6 = p[(i + 6) * rs];
        float4 a7 = p[(i + 7) * rs];
        sx += __expf(a0.x) + __expf(a1.x) + __expf(a2.x) + __expf(a3.x)
            + __expf(a4.x) + __expf(a5.x) + __expf(a6.x) + __expf(a7.x);
        sy += __expf(a0.y) + __expf(a1.y) + __expf(a2.y) + __expf(a3.y)
            + __expf(a4.y) + __expf(a5.y) + __expf(a6.y) + __expf(a7.y);
        sz += __expf(a0.z) + __expf(a1.z) + __expf(a2.z) + __expf(a3.z)
            + __expf(a4.z) + __expf(a5.z) + __expf(a6.z) + __expf(a7.z);
        sw += __expf(a0.w) + __expf(a1.w) + __expf(a2.w) + __expf(a3.w)
            + __expf(a4.w) + __expf(a5.w) + __expf(a6.w) + __expf(a7.w);
    }
    float4 r = make_float4(sx, sy, sz, sw);
    ((float4*)(g_Ep + ((size_t)blockIdx.x * BATCH + b) * KK))[t] = r;
}

// ---------------------------------------------------------------------------
// Kernel 2 (tiny): ew[b,i] = exp(P0[b,i]) * K / E1[b,i].
// grid = BATCH, block = 512.
// ---------------------------------------------------------------------------
__global__ void __launch_bounds__(512) k_combine(const float* __restrict__ P0)
{
    const int b = blockIdx.x;
    const int i = threadIdx.x;
    float e1 = 0.f;
#pragma unroll
    for (int s = 0; s < NSL; s++)
        e1 += g_Ep[((size_t)(NSL + s) * BATCH + b) * KK + i];
    g_ew[b * KK + i] = __expf(P0[b * KK + i]) * (float)KK / e1;
}

// ---------------------------------------------------------------------------
// Kernel 3: partial mm[b,j] = sum_{i in slice} ew[b,i]*exp(P1[b,i,j]).
// grid = (NSL, BATCH), block = 128; thread owns 4 cols (float4).
// ---------------------------------------------------------------------------
__global__ void __launch_bounds__(TPB) k_mid(const float* __restrict__ P1)
{
    const int slice = blockIdx.x;
    const int b     = blockIdx.y;
    const int t     = threadIdx.x;

    __shared__ float ew[32];
    if (t < 32) ew[t] = g_ew[b * KK + slice * 32 + t];
    __syncthreads();

    const float4* p = (const float4*)(P1 + (size_t)b * KK * KK
                                         + (size_t)(slice * 32) * KK) + t;
    const int rs = KK / 4;

    float sx = 0.f, sy = 0.f, sz = 0.f, sw = 0.f;
#pragma unroll
    for (int i = 0; i < 32; i += 4) {
        float4 a0 = p[(i + 0) * rs];
        float4 a1 = p[(i + 1) * rs];
        float4 a2 = p[(i + 2) * rs];
        float4 a3 = p[(i + 3) * rs];
        float w0 = ew[i + 0], w1 = ew[i + 1], w2 = ew[i + 2], w3 = ew[i + 3];
        sx += w0 * __expf(a0.x) + w1 * __expf(a1.x)
            + w2 * __expf(a2.x) + w3 * __expf(a3.x);
        sy += w0 * __expf(a0.y) + w1 * __expf(a1.y)
            + w2 * __expf(a2.y) + w3 * __expf(a3.y);
        sz += w0 * __expf(a0.z) + w1 * __expf(a1.z)
            + w2 * __expf(a2.z) + w3 * __expf(a3.z);
        sw += w0 * __expf(a0.w) + w1 * __expf(a1.w)
            + w2 * __expf(a2.w) + w3 * __expf(a3.w);
    }
    float4 r = make_float4(sx, sy, sz, sw);
    ((float4*)(g_mmp + ((size_t)slice * BATCH + b) * KK))[t] = r;
}

// ---------------------------------------------------------------------------
// Kernel 4 (fused final): s[b] = sum_j (Σ_s mmp)/(Σ_s E0p) * exp(P2[b,j]);
// g_sb[b] = logK - log(s[b]); last-finishing block does the deterministic
// tree-sum over batches into out[0] and resets the ticket.
// grid = BATCH, block = 128; thread owns 4 j's (float4).
// ---------------------------------------------------------------------------
__global__ void __launch_bounds__(TPB) k_final(const float* __restrict__ P2,
                                               float* __restrict__ out)
{
    const int b = blockIdx.x;
    const int t = threadIdx.x;

    float4 m  = make_float4(0.f, 0.f, 0.f, 0.f);
    float4 e0 = make_float4(0.f, 0.f, 0.f, 0.f);
#pragma unroll
    for (int s = 0; s < NSL; s++) {
        float4 a = ((const float4*)(g_mmp + ((size_t)s * BATCH + b) * KK))[t];
        float4 c = ((const float4*)(g_Ep  + ((size_t)s * BATCH + b) * KK))[t];
        m.x += a.x;  m.y += a.y;  m.z += a.z;  m.w += a.w;
        e0.x += c.x; e0.y += c.y; e0.z += c.z; e0.w += c.w;
    }
    float4 p2 = ((const float4*)(P2 + (size_t)b * KK))[t];
    float acc = m.x / e0.x * __expf(p2.x)
              + m.y / e0.y * __expf(p2.y)
              + m.z / e0.z * __expf(p2.z)
              + m.w / e0.w * __expf(p2.w);

#pragma unroll
    for (int o = 16; o; o >>= 1)
        acc += __shfl_down_sync(0xFFFFFFFFu, acc, o);

    __shared__ float red[4];
    if ((t & 31) == 0) red[t >> 5] = acc;
    __syncthreads();

    __shared__ bool amLast;
    if (t == 0) {
        float r = (red[0] + red[1]) + (red[2] + red[3]);
        g_sb[b] = LOGK - logf(r);
        __threadfence();
        unsigned int n = atomicAdd(&g_ticket, 1u);
        amLast = (n == BATCH - 1);
    }
    __syncthreads();

    if (amLast) {
        __shared__ float sm[BATCH];
        if (t < BATCH) sm[t] = g_sb[t];
        __syncthreads();
#pragma unroll
        for (int off = BATCH / 2; off > 0; off >>= 1) {
            if (t < off) sm[t] += sm[t + off];
            __syncthreads();
        }
        if (t == 0) {
            out[0] = sm[0];
            g_ticket = 0;   // reset for graph replay
        }
    }
}

// ---------------------------------------------------------------------------
extern "C" void kernel_launch(void* const* d_in, const int* in_sizes, int n_in,
                              void* d_out, int out_size)
{
    const float* Q0 = (const float*)d_in[0];  // logQ0 [B,K,K]
    const float* Q1 = (const float*)d_in[1];  // logQ1 [B,K,K]
    const float* P0 = (const float*)d_in[2];  // logP0 [B,1,K]
    const float* P1 = (const float*)d_in[3];  // logP1 [B,K,K]
    const float* P2 = (const float*)d_in[4];  // logP2 [B,K,1]

    dim3 g1(2 * NSL, BATCH);
    k_colsum<<<g1, TPB>>>(Q0, Q1);

    k_combine<<<BATCH, 512>>>(P0);

    dim3 g3(NSL, BATCH);
    k_mid<<<g3, TPB>>>(P1);

    k_final<<<BATCH, TPB>>>(P2, (float*)d_out);
}

// round 5
// speedup vs baseline: 1.0153x; 1.0120x over previous
#include <cuda_runtime.h>
#include <math.h>

#define BATCH  128
#define KK     512
#define NSL    16     // i-slices of 32 rows
#define TPB    128    // big kernels: thread owns 4 columns (float4)
#define JSPL   4      // j-chunks in k_final

#define LOGK 6.2383246250395077632f   // log(512)

// Scratch (__device__ globals; allocation-free rule). Fully overwritten per launch.
__device__ float g_Ep[2 * NSL * BATCH * KK];   // partial col-sums Q0/Q1 (8 MB)
__device__ float g_mmp[NSL * BATCH * KK];      // partial mm sums (4 MB)
__device__ float g_ew[BATCH * KK];             // exp(P0)*K/E1 (256 KB)
__device__ float g_E0inv[BATCH * KK];          // 1/E0 (256 KB)
__device__ float g_sp[BATCH * JSPL];           // per-(b,chunk) t partial sums
__device__ unsigned int g_ticket;              // zero-init; last block resets

// ---------------------------------------------------------------------------
// Kernel 1: partial column sums of exp() for Q0 and Q1, float4-vectorized.
// grid = (32, BATCH): x = which*16 + slice. block = 128; thread owns 4 cols.
// ---------------------------------------------------------------------------
__global__ void __launch_bounds__(TPB) k_colsum(const float* __restrict__ Q0,
                                                const float* __restrict__ Q1)
{
    const int which = blockIdx.x >> 4;
    const int slice = blockIdx.x & 15;
    const int b     = blockIdx.y;
    const int t     = threadIdx.x;

    const float* __restrict__ src = which ? Q1 : Q0;
    const float4* p = (const float4*)(src + (size_t)b * KK * KK
                                          + (size_t)(slice * 32) * KK) + t;
    const int rs = KK / 4;   // row stride in float4

    float sx = 0.f, sy = 0.f, sz = 0.f, sw = 0.f;
#pragma unroll
    for (int i = 0; i < 32; i += 8) {
        float4 a0 = p[(i + 0) * rs];
        float4 a1 = p[(i + 1) * rs];
        float4 a2 = p[(i + 2) * rs];
        float4 a3 = p[(i + 3) * rs];
        float4 a4 = p[(i + 4) * rs];
        float4 a5 = p[(i + 5) * rs];
        float4 a6 = p[(i + 6) * rs];
        float4 a7 = p[(i + 7) * rs];
        sx += __expf(a0.x) + __expf(a1.x) + __expf(a2.x) + __expf(a3.x)
            + __expf(a4.x) + __expf(a5.x) + __expf(a6.x) + __expf(a7.x);
        sy += __expf(a0.y) + __expf(a1.y) + __expf(a2.y) + __expf(a3.y)
            + __expf(a4.y) + __expf(a5.y) + __expf(a6.y) + __expf(a7.y);
        sz += __expf(a0.z) + __expf(a1.z) + __expf(a2.z) + __expf(a3.z)
            + __expf(a4.z) + __expf(a5.z) + __expf(a6.z) + __expf(a7.z);
        sw += __expf(a0.w) + __expf(a1.w) + __expf(a2.w) + __expf(a3.w)
            + __expf(a4.w) + __expf(a5.w) + __expf(a6.w) + __expf(a7.w);
    }
    ((float4*)(g_Ep + ((size_t)blockIdx.x * BATCH + b) * KK))[t] =
        make_float4(sx, sy, sz, sw);
}

// ---------------------------------------------------------------------------
// Kernel 2: reduce BOTH g_Ep halves -> ew[b,i] = exp(P0)*K/E1, E0inv[b,j]=1/E0.
// grid = BATCH, block = 512. 32 independent strided loads per thread.
// ---------------------------------------------------------------------------
__global__ void __launch_bounds__(512) k_combine(const float* __restrict__ P0)
{
    const int b = blockIdx.x;
    const int i = threadIdx.x;
    const int base = b * KK + i;

    float e0 = 0.f, e1 = 0.f;
#pragma unroll
    for (int s = 0; s < NSL; s++) {
        e0 += g_Ep[((size_t)s         * BATCH + b) * KK + i];
        e1 += g_Ep[((size_t)(NSL + s) * BATCH + b) * KK + i];
    }
    g_E0inv[base] = 1.0f / e0;
    g_ew[base]    = __expf(P0[base]) * (float)KK / e1;
}

// ---------------------------------------------------------------------------
// Kernel 3: partial mm[b,j] = sum_{i in slice} ew[b,i]*exp(P1[b,i,j]).
// grid = (NSL, BATCH), block = 128; thread owns 4 cols (float4).
// ---------------------------------------------------------------------------
__global__ void __launch_bounds__(TPB) k_mid(const float* __restrict__ P1)
{
    const int slice = blockIdx.x;
    const int b     = blockIdx.y;
    const int t     = threadIdx.x;

    __shared__ float ew[32];
    if (t < 32) ew[t] = g_ew[b * KK + slice * 32 + t];
    __syncthreads();

    const float4* p = (const float4*)(P1 + (size_t)b * KK * KK
                                         + (size_t)(slice * 32) * KK) + t;
    const int rs = KK / 4;

    float sx = 0.f, sy = 0.f, sz = 0.f, sw = 0.f;
#pragma unroll
    for (int i = 0; i < 32; i += 4) {
        float4 a0 = p[(i + 0) * rs];
        float4 a1 = p[(i + 1) * rs];
        float4 a2 = p[(i + 2) * rs];
        float4 a3 = p[(i + 3) * rs];
        float w0 = ew[i + 0], w1 = ew[i + 1], w2 = ew[i + 2], w3 = ew[i + 3];
        sx += w0 * __expf(a0.x) + w1 * __expf(a1.x)
            + w2 * __expf(a2.x) + w3 * __expf(a3.x);
        sy += w0 * __expf(a0.y) + w1 * __expf(a1.y)
            + w2 * __expf(a2.y) + w3 * __expf(a3.y);
        sz += w0 * __expf(a0.z) + w1 * __expf(a1.z)
            + w2 * __expf(a2.z) + w3 * __expf(a3.z);
        sw += w0 * __expf(a0.w) + w1 * __expf(a1.w)
            + w2 * __expf(a2.w) + w3 * __expf(a3.w);
    }
    ((float4*)(g_mmp + ((size_t)slice * BATCH + b) * KK))[t] =
        make_float4(sx, sy, sz, sw);
}

// ---------------------------------------------------------------------------
// Kernel 4: t partials. grid = (JSPL, BATCH) = 512 blocks, block = 128.
// Thread owns one j = js*128 + t; reduces NSL mmp partials, applies
// E0inv * exp(P2), block-reduces -> g_sp[b*JSPL+js]. Last-finishing block
// (ticket) does the deterministic per-batch log + batch tree-sum into out.
// ---------------------------------------------------------------------------
__global__ void __launch_bounds__(TPB) k_final(const float* __restrict__ P2,
                                               float* __restrict__ out)
{
    const int js = blockIdx.x;
    const int b  = blockIdx.y;
    const int t  = threadIdx.x;
    const int j  = js * TPB + t;

    float m = 0.f;
#pragma unroll
    for (int s = 0; s < NSL; s++)
        m += g_mmp[((size_t)s * BATCH + b) * KK + j];

    float acc = m * g_E0inv[b * KK + j] * __expf(P2[b * KK + j]);

#pragma unroll
    for (int o = 16; o; o >>= 1)
        acc += __shfl_down_sync(0xFFFFFFFFu, acc, o);

    __shared__ float red[4];
    if ((t & 31) == 0) red[t >> 5] = acc;
    __syncthreads();

    __shared__ bool amLast;
    if (t == 0) {
        g_sp[b * JSPL + js] = (red[0] + red[1]) + (red[2] + red[3]);
        __threadfence();
        unsigned int n = atomicAdd(&g_ticket, 1u);
        amLast = (n == BATCH * JSPL - 1);
    }
    __syncthreads();

    if (amLast) {
        // 128 threads: one per batch; fixed-order sums -> deterministic.
        __shared__ float sm[BATCH];
        float s = (g_sp[t * JSPL + 0] + g_sp[t * JSPL + 1])
                + (g_sp[t * JSPL + 2] + g_sp[t * JSPL + 3]);
        sm[t] = LOGK - logf(s);
        __syncthreads();
#pragma unroll
        for (int off = BATCH / 2; off > 0; off >>= 1) {
            if (t < off) sm[t] += sm[t + off];
            __syncthreads();
        }
        if (t == 0) {
            out[0] = sm[0];
            g_ticket = 0;   // reset for graph replay
        }
    }
}

// ---------------------------------------------------------------------------
extern "C" void kernel_launch(void* const* d_in, const int* in_sizes, int n_in,
                              void* d_out, int out_size)
{
    const float* Q0 = (const float*)d_in[0];  // logQ0 [B,K,K]
    const float* Q1 = (const float*)d_in[1];  // logQ1 [B,K,K]
    const float* P0 = (const float*)d_in[2];  // logP0 [B,1,K]
    const float* P1 = (const float*)d_in[3];  // logP1 [B,K,K]
    const float* P2 = (const float*)d_in[4];  // logP2 [B,K,1]

    dim3 g1(2 * NSL, BATCH);
    k_colsum<<<g1, TPB>>>(Q0, Q1);

    k_combine<<<BATCH, 512>>>(P0);

    dim3 g3(NSL, BATCH);
    k_mid<<<g3, TPB>>>(P1);

    dim3 g4(JSPL, BATCH);
    k_final<<<g4, TPB>>>(P2, (float*)d_out);
}

// round 6
// speedup vs baseline: 1.0541x; 1.0382x over previous
#include <cuda_runtime.h>
#include <math.h>

#define BATCH  128
#define KK     512
#define NSL    8      // i-slices of 64 rows
#define SLR    64     // rows per slice
#define TPB    128    // big kernels: thread owns 4 columns (float4)
#define JSPL   4      // j-chunks in k_final

#define LOGK 6.2383246250395077632f   // log(512)

// Scratch (__device__ globals; allocation-free rule). Fully overwritten per launch.
__device__ float g_Ep[2 * NSL * BATCH * KK];   // partial col-sums Q0/Q1 (4 MB)
__device__ float g_mmp[NSL * BATCH * KK];      // partial mm sums (2 MB)
__device__ float g_ew[BATCH * KK];             // exp(P0)*K/E1 (256 KB)
__device__ float g_E0inv[BATCH * KK];          // 1/E0 (256 KB)
__device__ float g_sp[BATCH * JSPL];           // per-(b,chunk) t partial sums
__device__ unsigned int g_ticket;              // zero-init; last block resets

// ---------------------------------------------------------------------------
// Kernel 1: partial column sums of exp() for Q0 and Q1, float4-vectorized.
// grid = (2*NSL, BATCH): x = which*NSL + slice. block = 128; 64 rows/block.
// ---------------------------------------------------------------------------
__global__ void __launch_bounds__(TPB) k_colsum(const float* __restrict__ Q0,
                                                const float* __restrict__ Q1)
{
    const int which = blockIdx.x >> 3;
    const int slice = blockIdx.x & 7;
    const int b     = blockIdx.y;
    const int t     = threadIdx.x;

    const float* __restrict__ src = which ? Q1 : Q0;
    const float4* p = (const float4*)(src + (size_t)b * KK * KK
                                          + (size_t)(slice * SLR) * KK) + t;
    const int rs = KK / 4;   // row stride in float4

    float sx = 0.f, sy = 0.f, sz = 0.f, sw = 0.f;
#pragma unroll
    for (int i = 0; i < SLR; i += 8) {
        float4 a0 = p[(i + 0) * rs];
        float4 a1 = p[(i + 1) * rs];
        float4 a2 = p[(i + 2) * rs];
        float4 a3 = p[(i + 3) * rs];
        float4 a4 = p[(i + 4) * rs];
        float4 a5 = p[(i + 5) * rs];
        float4 a6 = p[(i + 6) * rs];
        float4 a7 = p[(i + 7) * rs];
        sx += __expf(a0.x) + __expf(a1.x) + __expf(a2.x) + __expf(a3.x)
            + __expf(a4.x) + __expf(a5.x) + __expf(a6.x) + __expf(a7.x);
        sy += __expf(a0.y) + __expf(a1.y) + __expf(a2.y) + __expf(a3.y)
            + __expf(a4.y) + __expf(a5.y) + __expf(a6.y) + __expf(a7.y);
        sz += __expf(a0.z) + __expf(a1.z) + __expf(a2.z) + __expf(a3.z)
            + __expf(a4.z) + __expf(a5.z) + __expf(a6.z) + __expf(a7.z);
        sw += __expf(a0.w) + __expf(a1.w) + __expf(a2.w) + __expf(a3.w)
            + __expf(a4.w) + __expf(a5.w) + __expf(a6.w) + __expf(a7.w);
    }
    ((float4*)(g_Ep + ((size_t)blockIdx.x * BATCH + b) * KK))[t] =
        make_float4(sx, sy, sz, sw);
}

// ---------------------------------------------------------------------------
// Kernel 2: reduce g_Ep -> ew[b,i] = exp(P0)*K/E1, E0inv[b,j] = 1/E0.
// grid = BATCH, block = 512. 16 independent strided loads per thread.
// ---------------------------------------------------------------------------
__global__ void __launch_bounds__(512) k_combine(const float* __restrict__ P0)
{
    const int b = blockIdx.x;
    const int i = threadIdx.x;
    const int base = b * KK + i;

    float e0 = 0.f, e1 = 0.f;
#pragma unroll
    for (int s = 0; s < NSL; s++) {
        e0 += g_Ep[((size_t)s         * BATCH + b) * KK + i];
        e1 += g_Ep[((size_t)(NSL + s) * BATCH + b) * KK + i];
    }
    g_E0inv[base] = 1.0f / e0;
    g_ew[base]    = __expf(P0[base]) * (float)KK / e1;
}

// ---------------------------------------------------------------------------
// Kernel 3: partial mm[b,j] = sum_{i in slice} ew[b,i]*exp(P1[b,i,j]).
// grid = (NSL, BATCH), block = 128; thread owns 4 cols (float4); 64 rows.
// 8 float4 loads batched ahead of the exp chain -> 128 B in flight/thread.
// ---------------------------------------------------------------------------
__global__ void __launch_bounds__(TPB) k_mid(const float* __restrict__ P1)
{
    const int slice = blockIdx.x;
    const int b     = blockIdx.y;
    const int t     = threadIdx.x;

    __shared__ float ew[SLR];
    if (t < SLR) ew[t] = g_ew[b * KK + slice * SLR + t];
    __syncthreads();

    const float4* p = (const float4*)(P1 + (size_t)b * KK * KK
                                         + (size_t)(slice * SLR) * KK) + t;
    const int rs = KK / 4;

    float sx = 0.f, sy = 0.f, sz = 0.f, sw = 0.f;
#pragma unroll
    for (int i = 0; i < SLR; i += 8) {
        float4 a0 = p[(i + 0) * rs];
        float4 a1 = p[(i + 1) * rs];
        float4 a2 = p[(i + 2) * rs];
        float4 a3 = p[(i + 3) * rs];
        float4 a4 = p[(i + 4) * rs];
        float4 a5 = p[(i + 5) * rs];
        float4 a6 = p[(i + 6) * rs];
        float4 a7 = p[(i + 7) * rs];
        float w0 = ew[i + 0], w1 = ew[i + 1], w2 = ew[i + 2], w3 = ew[i + 3];
        float w4 = ew[i + 4], w5 = ew[i + 5], w6 = ew[i + 6], w7 = ew[i + 7];
        sx += w0 * __expf(a0.x) + w1 * __expf(a1.x)
            + w2 * __expf(a2.x) + w3 * __expf(a3.x)
            + w4 * __expf(a4.x) + w5 * __expf(a5.x)
            + w6 * __expf(a6.x) + w7 * __expf(a7.x);
        sy += w0 * __expf(a0.y) + w1 * __expf(a1.y)
            + w2 * __expf(a2.y) + w3 * __expf(a3.y)
            + w4 * __expf(a4.y) + w5 * __expf(a5.y)
            + w6 * __expf(a6.y) + w7 * __expf(a7.y);
        sz += w0 * __expf(a0.z) + w1 * __expf(a1.z)
            + w2 * __expf(a2.z) + w3 * __expf(a3.z)
            + w4 * __expf(a4.z) + w5 * __expf(a5.z)
            + w6 * __expf(a6.z) + w7 * __expf(a7.z);
        sw += w0 * __expf(a0.w) + w1 * __expf(a1.w)
            + w2 * __expf(a2.w) + w3 * __expf(a3.w)
            + w4 * __expf(a4.w) + w5 * __expf(a5.w)
            + w6 * __expf(a6.w) + w7 * __expf(a7.w);
    }
    ((float4*)(g_mmp + ((size_t)slice * BATCH + b) * KK))[t] =
        make_float4(sx, sy, sz, sw);
}

// ---------------------------------------------------------------------------
// Kernel 4: t partials. grid = (JSPL, BATCH) = 512 blocks, block = 128.
// Thread owns one j; reduces NSL mmp partials, applies E0inv*exp(P2),
// block-reduces -> g_sp. Last-finishing block (ticket) does the deterministic
// per-batch log + batch tree-sum into out and resets the ticket.
// ---------------------------------------------------------------------------
__global__ void __launch_bounds__(TPB) k_final(const float* __restrict__ P2,
                                               float* __restrict__ out)
{
    const int js = blockIdx.x;
    const int b  = blockIdx.y;
    const int t  = threadIdx.x;
    const int j  = js * TPB + t;

    float m = 0.f;
#pragma unroll
    for (int s = 0; s < NSL; s++)
        m += g_mmp[((size_t)s * BATCH + b) * KK + j];

    float acc = m * g_E0inv[b * KK + j] * __expf(P2[b * KK + j]);

#pragma unroll
    for (int o = 16; o; o >>= 1)
        acc += __shfl_down_sync(0xFFFFFFFFu, acc, o);

    __shared__ float red[4];
    if ((t & 31) == 0) red[t >> 5] = acc;
    __syncthreads();

    __shared__ bool amLast;
    if (t == 0) {
        g_sp[b * JSPL + js] = (red[0] + red[1]) + (red[2] + red[3]);
        __threadfence();
        unsigned int n = atomicAdd(&g_ticket, 1u);
        amLast = (n == BATCH * JSPL - 1);
    }
    __syncthreads();

    if (amLast) {
        // 128 threads: one per batch; fixed-order sums -> deterministic.
        __shared__ float sm[BATCH];
        float s = (g_sp[t * JSPL + 0] + g_sp[t * JSPL + 1])
                + (g_sp[t * JSPL + 2] + g_sp[t * JSPL + 3]);
        sm[t] = LOGK - logf(s);
        __syncthreads();
#pragma unroll
        for (int off = BATCH / 2; off > 0; off >>= 1) {
            if (t < off) sm[t] += sm[t + off];
            __syncthreads();
        }
        if (t == 0) {
            out[0] = sm[0];
            g_ticket = 0;   // reset for graph replay
        }
    }
}

// ---------------------------------------------------------------------------
extern "C" void kernel_launch(void* const* d_in, const int* in_sizes, int n_in,
                              void* d_out, int out_size)
{
    const float* Q0 = (const float*)d_in[0];  // logQ0 [B,K,K]
    const float* Q1 = (const float*)d_in[1];  // logQ1 [B,K,K]
    const float* P0 = (const float*)d_in[2];  // logP0 [B,1,K]
    const float* P1 = (const float*)d_in[3];  // logP1 [B,K,K]
    const float* P2 = (const float*)d_in[4];  // logP2 [B,K,1]

    dim3 g1(2 * NSL, BATCH);
    k_colsum<<<g1, TPB>>>(Q0, Q1);

    k_combine<<<BATCH, 512>>>(P0);

    dim3 g3(NSL, BATCH);
    k_mid<<<g3, TPB>>>(P1);

    dim3 g4(JSPL, BATCH);
    k_final<<<g4, TPB>>>(P2, (float*)d_out);
}

// round 7
// speedup vs baseline: 1.0586x; 1.0043x over previous
#include <cuda_runtime.h>
#include <math.h>

#define BATCH  128
#define KK     512
#define NSL    8      // i-slices of 64 rows
#define SLR    64     // rows per slice
#define TPB    128    // thread owns 4 columns (float4)

#define LOGK 6.2383246250395077632f   // log(512)

// Scratch (__device__ globals; allocation-free rule). Fully overwritten per launch.
__device__ float g_Ep[2 * NSL * BATCH * KK];   // partial col-sums Q0/Q1 (4 MB)
__device__ float g_mmp[NSL * BATCH * KK];      // partial mm sums (2 MB)
__device__ float g_ew[BATCH * KK];             // exp(P0)*K/E1
__device__ float g_E0inv[BATCH * KK];          // 1/E0
__device__ float g_sb[BATCH];                  // per-batch logK - log(sum_j t)
__device__ unsigned int g_tickA[BATCH];        // per-batch tickets, kernel 1
__device__ unsigned int g_tickB[BATCH];        // per-batch tickets, kernel 2
__device__ unsigned int g_tickF;               // global final ticket

__device__ __forceinline__ float4 ldcs4(const float4* p) {
    return __ldcs(p);
}

// ---------------------------------------------------------------------------
// Kernel 1: partial column sums of exp() for Q0 and Q1 (float4, streaming).
// grid = (2*NSL, BATCH). Last-finishing block of each batch computes
// ew[b,:] = exp(P0)*K/E1 and E0inv[b,:] = 1/E0 from the L2-hot partials.
// ---------------------------------------------------------------------------
__global__ void __launch_bounds__(TPB) k_colsum(const float* __restrict__ Q0,
                                                const float* __restrict__ Q1,
                                                const float* __restrict__ P0)
{
    const int which = blockIdx.x >> 3;
    const int slice = blockIdx.x & 7;
    const int b     = blockIdx.y;
    const int t     = threadIdx.x;

    const float* __restrict__ src = which ? Q1 : Q0;
    const float4* p = (const float4*)(src + (size_t)b * KK * KK
                                          + (size_t)(slice * SLR) * KK) + t;
    const int rs = KK / 4;

    float sx = 0.f, sy = 0.f, sz = 0.f, sw = 0.f;
#pragma unroll
    for (int i = 0; i < SLR; i += 8) {
        float4 a0 = ldcs4(p + (i + 0) * rs);
        float4 a1 = ldcs4(p + (i + 1) * rs);
        float4 a2 = ldcs4(p + (i + 2) * rs);
        float4 a3 = ldcs4(p + (i + 3) * rs);
        float4 a4 = ldcs4(p + (i + 4) * rs);
        float4 a5 = ldcs4(p + (i + 5) * rs);
        float4 a6 = ldcs4(p + (i + 6) * rs);
        float4 a7 = ldcs4(p + (i + 7) * rs);
        sx += __expf(a0.x) + __expf(a1.x) + __expf(a2.x) + __expf(a3.x)
            + __expf(a4.x) + __expf(a5.x) + __expf(a6.x) + __expf(a7.x);
        sy += __expf(a0.y) + __expf(a1.y) + __expf(a2.y) + __expf(a3.y)
            + __expf(a4.y) + __expf(a5.y) + __expf(a6.y) + __expf(a7.y);
        sz += __expf(a0.z) + __expf(a1.z) + __expf(a2.z) + __expf(a3.z)
            + __expf(a4.z) + __expf(a5.z) + __expf(a6.z) + __expf(a7.z);
        sw += __expf(a0.w) + __expf(a1.w) + __expf(a2.w) + __expf(a3.w)
            + __expf(a4.w) + __expf(a5.w) + __expf(a6.w) + __expf(a7.w);
    }
    ((float4*)(g_Ep + ((size_t)blockIdx.x * BATCH + b) * KK))[t] =
        make_float4(sx, sy, sz, sw);

    // --- per-batch ticket epilogue: last of 16 blocks builds ew / E0inv ---
    __threadfence();              // make this thread's partial store visible
    __syncthreads();
    __shared__ bool amLast;
    if (t == 0)
        amLast = (atomicAdd(&g_tickA[b], 1u) == 2 * NSL - 1);
    __syncthreads();

    if (amLast) {
#pragma unroll
        for (int c = 0; c < 4; c++) {
            const int i = c * TPB + t;
            float e0 = 0.f, e1 = 0.f;
#pragma unroll
            for (int s = 0; s < NSL; s++) {
                e0 += g_Ep[((size_t)s         * BATCH + b) * KK + i];
                e1 += g_Ep[((size_t)(NSL + s) * BATCH + b) * KK + i];
            }
            g_E0inv[b * KK + i] = 1.0f / e0;
            g_ew[b * KK + i]    = __expf(P0[b * KK + i]) * (float)KK / e1;
        }
        if (t == 0) g_tickA[b] = 0;   // reset for graph replay
    }
}

// ---------------------------------------------------------------------------
// Kernel 2: partial mm[b,j] = sum_{i in slice} ew[b,i]*exp(P1[b,i,j]).
// Last-finishing block of each batch computes s[b] and g_sb[b]; the final
// global ticket makes one block do the deterministic batch tree-sum -> out.
// grid = (NSL, BATCH), block = 128.
// ---------------------------------------------------------------------------
__global__ void __launch_bounds__(TPB) k_mid(const float* __restrict__ P1,
                                             const float* __restrict__ P2,
                                             float* __restrict__ out)
{
    const int slice = blockIdx.x;
    const int b     = blockIdx.y;
    const int t     = threadIdx.x;

    __shared__ float ew[SLR];
    if (t < SLR) ew[t] = g_ew[b * KK + slice * SLR + t];
    __syncthreads();

    const float4* p = (const float4*)(P1 + (size_t)b * KK * KK
                                         + (size_t)(slice * SLR) * KK) + t;
    const int rs = KK / 4;

    float sx = 0.f, sy = 0.f, sz = 0.f, sw = 0.f;
#pragma unroll
    for (int i = 0; i < SLR; i += 8) {
        float4 a0 = ldcs4(p + (i + 0) * rs);
        float4 a1 = ldcs4(p + (i + 1) * rs);
        float4 a2 = ldcs4(p + (i + 2) * rs);
        float4 a3 = ldcs4(p + (i + 3) * rs);
        float4 a4 = ldcs4(p + (i + 4) * rs);
        float4 a5 = ldcs4(p + (i + 5) * rs);
        float4 a6 = ldcs4(p + (i + 6) * rs);
        float4 a7 = ldcs4(p + (i + 7) * rs);
        float w0 = ew[i + 0], w1 = ew[i + 1], w2 = ew[i + 2], w3 = ew[i + 3];
        float w4 = ew[i + 4], w5 = ew[i + 5], w6 = ew[i + 6], w7 = ew[i + 7];
        sx += w0 * __expf(a0.x) + w1 * __expf(a1.x)
            + w2 * __expf(a2.x) + w3 * __expf(a3.x)
            + w4 * __expf(a4.x) + w5 * __expf(a5.x)
            + w6 * __expf(a6.x) + w7 * __expf(a7.x);
        sy += w0 * __expf(a0.y) + w1 * __expf(a1.y)
            + w2 * __expf(a2.y) + w3 * __expf(a3.y)
            + w4 * __expf(a4.y) + w5 * __expf(a5.y)
            + w6 * __expf(a6.y) + w7 * __expf(a7.y);
        sz += w0 * __expf(a0.z) + w1 * __expf(a1.z)
            + w2 * __expf(a2.z) + w3 * __expf(a3.z)
            + w4 * __expf(a4.z) + w5 * __expf(a5.z)
            + w6 * __expf(a6.z) + w7 * __expf(a7.z);
        sw += w0 * __expf(a0.w) + w1 * __expf(a1.w)
            + w2 * __expf(a2.w) + w3 * __expf(a3.w)
            + w4 * __expf(a4.w) + w5 * __expf(a5.w)
            + w6 * __expf(a6.w) + w7 * __expf(a7.w);
    }
    ((float4*)(g_mmp + ((size_t)slice * BATCH + b) * KK))[t] =
        make_float4(sx, sy, sz, sw);

    // --- per-batch ticket epilogue: last of 8 blocks finishes batch b ---
    __threadfence();
    __syncthreads();
    __shared__ bool amLast;
    if (t == 0)
        amLast = (atomicAdd(&g_tickB[b], 1u) == NSL - 1);
    __syncthreads();

    if (amLast) {
        float acc = 0.f;
#pragma unroll
        for (int c = 0; c < 4; c++) {
            const int j = c * TPB + t;
            float m = 0.f;
#pragma unroll
            for (int s = 0; s < NSL; s++)
                m += g_mmp[((size_t)s * BATCH + b) * KK + j];
            acc += m * g_E0inv[b * KK + j] * __expf(P2[b * KK + j]);
        }
#pragma unroll
        for (int o = 16; o; o >>= 1)
            acc += __shfl_down_sync(0xFFFFFFFFu, acc, o);

        __shared__ float red[4];
        if ((t & 31) == 0) red[t >> 5] = acc;
        __syncthreads();

        __shared__ bool amFinal;
        if (t == 0) {
            float r = (red[0] + red[1]) + (red[2] + red[3]);
            g_sb[b] = LOGK - logf(r);
            g_tickB[b] = 0;           // reset for graph replay
            __threadfence();
            amFinal = (atomicAdd(&g_tickF, 1u) == BATCH - 1);
        }
        __syncthreads();

        if (amFinal) {
            // one block: fixed-order tree sum over batches -> deterministic
            __shared__ float sm[BATCH];
            sm[t] = g_sb[t];
            __syncthreads();
#pragma unroll
            for (int off = BATCH / 2; off > 0; off >>= 1) {
                if (t < off) sm[t] += sm[t + off];
                __syncthreads();
            }
            if (t == 0) {
                out[0] = sm[0];
                g_tickF = 0;          // reset for graph replay
            }
        }
    }
}

// ---------------------------------------------------------------------------
extern "C" void kernel_launch(void* const* d_in, const int* in_sizes, int n_in,
                              void* d_out, int out_size)
{
    const float* Q0 = (const float*)d_in[0];  // logQ0 [B,K,K]
    const float* Q1 = (const float*)d_in[1];  // logQ1 [B,K,K]
    const float* P0 = (const float*)d_in[2];  // logP0 [B,1,K]
    const float* P1 = (const float*)d_in[3];  // logP1 [B,K,K]
    const float* P2 = (const float*)d_in[4];  // logP2 [B,K,1]

    dim3 g1(2 * NSL, BATCH);
    k_colsum<<<g1, TPB>>>(Q0, Q1, P0);

    dim3 g2(NSL, BATCH);
    k_mid<<<g2, TPB>>>(P1, P2, (float*)d_out);
}